// round 16
// baseline (speedup 1.0000x reference)
#include <cuda_runtime.h>
#include <math.h>
#include <stdint.h>

// Multiresolution hash-grid encoding, spatially-sorted gather (v6).
//
// Two independent point chunks, sorted + encoded with fork/join stream
// overlap inside the captured graph:
//   stream0: histA -> scanA -> scatA -> mainA
//   stream2:             (after scatA) histB -> scanB -> scatB -> mainB
// The L1tex-bound main kernel of chunk A overlaps the L2/atomic-bound sort
// of chunk B, hiding most of the sort pipeline.
//
// Main kernel = R14 exact form: x-pair float4 hash merge + predicated odd
// loads, smem-staged warp-transposed output stores (4 wf per STG.128).

#define N_LEVELS 16
#define LOG2_T   19
#define T_MASK   ((1u << LOG2_T) - 1u)
#define P1       2654435761u
#define P2       805459861u

#define SORT_RES   32
#define N_BUCKETS  (SORT_RES * SORT_RES * SORT_RES)   // 2^15
#define MAX_N      1100000

#define TPB       256
#define ROW_PAD   9          // float4 units per smem row (8 data + 1 pad)

__device__ unsigned g_hist[2][N_BUCKETS];   // zero-init; scan restores zeros
__device__ unsigned g_base[2][N_BUCKETS];
__device__ unsigned g_key[MAX_N];           // bucket | rank<<15
__device__ float4   g_xs[MAX_N];            // sorted (x,y,z, idx-as-bits)

struct Params { float resf[N_LEVELS]; };

// ------------------------------------------------------------------ morton
__device__ __forceinline__ unsigned expand_bits(unsigned v) {
    v = (v * 0x00010001u) & 0xFF0000FFu;
    v = (v * 0x00000101u) & 0x0F00F00Fu;
    v = (v * 0x00000011u) & 0xC30C30C3u;
    v = (v * 0x00000005u) & 0x49249249u;
    return v;
}

__device__ __forceinline__ unsigned bucket_of(float px, float py, float pz) {
    int cx = (int)(px * (float)SORT_RES);
    int cy = (int)(py * (float)SORT_RES);
    int cz = (int)(pz * (float)SORT_RES);
    cx = min(max(cx, 0), SORT_RES - 1);
    cy = min(max(cy, 0), SORT_RES - 1);
    cz = min(max(cz, 0), SORT_RES - 1);
    return expand_bits((unsigned)cx)
         | (expand_bits((unsigned)cy) << 1)
         | (expand_bits((unsigned)cz) << 2);
}

// ---------------------------------------------------------------- sorting
__global__ __launch_bounds__(TPB) void hist_kernel(
    const float* __restrict__ x, int start, int cnt, int chunk)
{
    int i = blockIdx.x * TPB + threadIdx.x;
    if (i >= cnt) return;
    const int n = start + i;
    unsigned b = bucket_of(x[n * 3 + 0], x[n * 3 + 1], x[n * 3 + 2]);
    unsigned r = atomicAdd(&g_hist[chunk][b], 1u);
    g_key[n] = b | (r << 15);
}

__global__ __launch_bounds__(1024) void scan_kernel(int chunk) {
    __shared__ unsigned partial[1024];
    const int t = threadIdx.x;
    unsigned local[32];
    unsigned s = 0;
    #pragma unroll
    for (int j = 0; j < 32; ++j) {
        local[j] = g_hist[chunk][t * 32 + j];
        g_hist[chunk][t * 32 + j] = 0u;     // restore zero-invariant
        s += local[j];
    }
    partial[t] = s;
    __syncthreads();
    for (int d = 1; d < 1024; d <<= 1) {
        unsigned v = (t >= d) ? partial[t - d] : 0u;
        __syncthreads();
        partial[t] += v;
        __syncthreads();
    }
    unsigned run = (t > 0) ? partial[t - 1] : 0u;
    #pragma unroll
    for (int j = 0; j < 32; ++j) { g_base[chunk][t * 32 + j] = run; run += local[j]; }
}

__global__ __launch_bounds__(TPB) void scatter_kernel(
    const float* __restrict__ x, int start, int cnt, int chunk)
{
    int i = blockIdx.x * TPB + threadIdx.x;
    if (i >= cnt) return;
    const int n = start + i;
    const unsigned k = g_key[n];
    const unsigned pos = g_base[chunk][k & (N_BUCKETS - 1)] + (k >> 15);
    g_xs[start + pos] = make_float4(x[n * 3 + 0], x[n * 3 + 1], x[n * 3 + 2],
                                    __int_as_float(n));
}

// ------------------------------------------------------------------- main
__global__ __launch_bounds__(TPB) void hashgrid_kernel(
    const float2* __restrict__ table,   // [T] float2
    float4* __restrict__ out,           // [N,8] float4 rows
    Params p, int start, int cnt)
{
    __shared__ float4 s_row[TPB * ROW_PAD];   // 36 KB
    __shared__ int    s_n[TPB];

    const int tid  = threadIdx.x;
    const int lane = tid & 31;
    const int i = blockIdx.x * TPB + tid;
    const bool valid = (i < cnt);

    int n = -1;
    if (valid) {
        const float4 xi = g_xs[start + i];    // coalesced
        const float px = xi.x, py = xi.y, pz = xi.z;
        n = __float_as_int(xi.w);

        #pragma unroll
        for (int l = 0; l < N_LEVELS; l += 2) {
            float2 pr[2];
            #pragma unroll
            for (int s = 0; s < 2; ++s) {
                const float res = p.resf[l + s];
                const float sx = px * res;
                const float sy = py * res;
                const float sz = pz * res;

                const float fx = floorf(sx);
                const float fy = floorf(sy);
                const float fz = floorf(sz);

                const float dx = sx - fx;
                const float dy = sy - fy;
                const float dz = sz - fz;

                const unsigned x0u = (unsigned)(int)fx;
                const unsigned hy0 = (unsigned)(int)fy * P1;
                const unsigned hy1 = hy0 + P1;
                const unsigned hz0 = (unsigned)(int)fz * P2;
                const unsigned hz1 = hz0 + P2;

                const unsigned g00 = hy0 ^ hz0;
                const unsigned g10 = hy1 ^ hz0;
                const unsigned g01 = hy0 ^ hz1;
                const unsigned g11 = hy1 ^ hz1;

                const unsigned h000 = (x0u ^ g00) & T_MASK;
                const unsigned h010 = (x0u ^ g10) & T_MASK;
                const unsigned h001 = (x0u ^ g01) & T_MASK;
                const unsigned h011 = (x0u ^ g11) & T_MASK;

                const unsigned x1u  = x0u + 1u;
                const unsigned h100 = (x1u ^ g00) & T_MASK;
                const unsigned h110 = (x1u ^ g10) & T_MASK;
                const unsigned h101 = (x1u ^ g01) & T_MASK;
                const unsigned h111 = (x1u ^ g11) & T_MASK;

                const bool xeven = (x0u & 1u) == 0u;

                const float4 q00 = __ldg((const float4*)&table[h000 & ~1u]);
                const float4 q10 = __ldg((const float4*)&table[h010 & ~1u]);
                const float4 q01 = __ldg((const float4*)&table[h001 & ~1u]);
                const float4 q11 = __ldg((const float4*)&table[h011 & ~1u]);

                float2 e00, e10, e01, e11;
                if (!xeven) {
                    e00 = __ldg(&table[h100]);
                    e10 = __ldg(&table[h110]);
                    e01 = __ldg(&table[h101]);
                    e11 = __ldg(&table[h111]);
                }

                const float2 q00lo = make_float2(q00.x, q00.y), q00hi = make_float2(q00.z, q00.w);
                const float2 q10lo = make_float2(q10.x, q10.y), q10hi = make_float2(q10.z, q10.w);
                const float2 q01lo = make_float2(q01.x, q01.y), q01hi = make_float2(q01.z, q01.w);
                const float2 q11lo = make_float2(q11.x, q11.y), q11hi = make_float2(q11.z, q11.w);

                const bool p00 = (h000 & 1u), p10 = (h010 & 1u),
                           p01 = (h001 & 1u), p11 = (h011 & 1u);

                const float2 v000 = p00 ? q00hi : q00lo;
                const float2 v010 = p10 ? q10hi : q10lo;
                const float2 v001 = p01 ? q01hi : q01lo;
                const float2 v011 = p11 ? q11hi : q11lo;

                const float2 v100 = xeven ? (p00 ? q00lo : q00hi) : e00;
                const float2 v110 = xeven ? (p10 ? q10lo : q10hi) : e10;
                const float2 v101 = xeven ? (p01 ? q01lo : q01hi) : e01;
                const float2 v111 = xeven ? (p11 ? q11lo : q11hi) : e11;

                const float wx0 = 1.0f - dx, wx1 = dx;
                const float wy0 = 1.0f - dy, wy1 = dy;
                const float wz0 = 1.0f - dz, wz1 = dz;

                float a00x = v000.x * wx0 + v100.x * wx1;
                float a00y = v000.y * wx0 + v100.y * wx1;
                float a10x = v010.x * wx0 + v110.x * wx1;
                float a10y = v010.y * wx0 + v110.y * wx1;
                float a01x = v001.x * wx0 + v101.x * wx1;
                float a01y = v001.y * wx0 + v101.y * wx1;
                float a11x = v011.x * wx0 + v111.x * wx1;
                float a11y = v011.y * wx0 + v111.y * wx1;

                float b0x = a00x * wy0 + a10x * wy1;
                float b0y = a00y * wy0 + a10y * wy1;
                float b1x = a01x * wy0 + a11x * wy1;
                float b1y = a01y * wy0 + a11y * wy1;

                pr[s].x = b0x * wz0 + b1x * wz1;
                pr[s].y = b0y * wz0 + b1y * wz1;
            }
            s_row[tid * ROW_PAD + (l >> 1)] =
                make_float4(pr[0].x, pr[0].y, pr[1].x, pr[1].y);
        }
    }
    s_n[tid] = n;
    __syncwarp();

    // Warp transpose store: 4 groups of 8 lanes each write one full 128B
    // output row contiguously -> 4 wavefronts per STG.128.
    const int wbase = tid & ~31;
    const int chunk = lane & 7;
    #pragma unroll
    for (int iter = 0; iter < 8; ++iter) {
        const int row = wbase + iter * 4 + (lane >> 3);
        const int nn = s_n[row];
        if (nn >= 0) {
            __stcs(&out[(size_t)nn * 8 + chunk], s_row[row * ROW_PAD + chunk]);
        }
    }
}

// ----------------------------------------------------------------- launch
extern "C" void kernel_launch(void* const* d_in, const int* in_sizes, int n_in,
                              void* d_out, int out_size)
{
    const float*  x     = (const float*)d_in[0];
    const float2* table = (const float2*)d_in[1];
    float4*       out   = (float4*)d_out;

    const int N = in_sizes[0] / 3;

    Params p;
    {
        const double growth = exp((log(128.0) - log(16.0)) / (double)(N_LEVELS - 1));
        for (int l = 0; l < N_LEVELS; ++l)
            p.resf[l] = (float)floor(16.0 * pow(growth, (double)l));
    }

    // Lazily-created side stream + events (first call is the uncaptured
    // correctness run; subsequent capture records the same fork/join DAG).
    static cudaStream_t s2 = nullptr;
    static cudaEvent_t  eFork = nullptr, eJoin = nullptr;
    if (s2 == nullptr) {
        cudaStreamCreateWithFlags(&s2, cudaStreamNonBlocking);
        cudaEventCreateWithFlags(&eFork, cudaEventDisableTiming);
        cudaEventCreateWithFlags(&eJoin, cudaEventDisableTiming);
    }

    // Two chunks: A = [0, NA), B = [NA, N)
    const int NA = ((N / 2) + TPB - 1) / TPB * TPB;
    const int NB = N - NA;
    const int pbA = (NA + TPB - 1) / TPB;
    const int pbB = (NB + TPB - 1) / TPB;

    // ---- chunk A sort (stream 0) ----
    hist_kernel<<<pbA, TPB>>>(x, 0, NA, 0);
    scan_kernel<<<1, 1024>>>(0);
    scatter_kernel<<<pbA, TPB>>>(x, 0, NA, 0);

    // fork: chunk B sort on s2, overlapping chunk A's main kernel
    cudaEventRecord(eFork, 0);
    cudaStreamWaitEvent(s2, eFork, 0);

    hist_kernel<<<pbB, TPB, 0, s2>>>(x, NA, NB, 1);
    scan_kernel<<<1, 1024, 0, s2>>>(1);
    scatter_kernel<<<pbB, TPB, 0, s2>>>(x, NA, NB, 1);
    hashgrid_kernel<<<pbB, TPB, 0, s2>>>(table, out, p, NA, NB);

    // chunk A main on stream 0 (concurrent with s2 chain)
    hashgrid_kernel<<<pbA, TPB>>>(table, out, p, 0, NA);

    // join
    cudaEventRecord(eJoin, s2);
    cudaStreamWaitEvent(0, eJoin, 0);
}

// round 17
// speedup vs baseline: 1.7899x; 1.7899x over previous
#include <cuda_runtime.h>
#include <math.h>
#include <stdint.h>

// Multiresolution hash-grid encoding, spatially-sorted gather (v7).
//
//  K1 hist      : 4 points/thread (MLP=4 on the rank atomics); Morton bucket
//                 (res 32); packed key = bucket | rank<<15, uint4 store.
//  K2a scan_loc : 32 blocks x 1024 thr: local exclusive scan of each
//                 1024-bucket slice into g_base, block total out, g_hist
//                 restored to zero (self-cleaning).
//  K2b scan_top : 32-thread warp scan of block totals -> g_boff.
//  K3 scatter   : 4 points/thread; pos = g_base[b] + g_boff[b>>10] + rank
//                 (no atomics); scattered float4(x,y,z,idx) stores, MLP=4.
//  K4 main      : R14 exact form -- one thread per sorted point, 16-level
//                 loop, x-pair float4 hash merge + predicated odd loads,
//                 smem-staged warp-transposed output stores.

#define N_LEVELS 16
#define LOG2_T   19
#define T_MASK   ((1u << LOG2_T) - 1u)
#define P1       2654435761u
#define P2       805459861u

#define SORT_RES   32
#define N_BUCKETS  (SORT_RES * SORT_RES * SORT_RES)   // 2^15
#define MAX_N      1100000

#define TPB       256
#define ROW_PAD   9          // float4 units per smem row (8 data + 1 pad)

__device__ unsigned g_hist[N_BUCKETS];   // zero-init; scan_loc restores zeros
__device__ unsigned g_base[N_BUCKETS];   // local-exclusive within 1024-slice
__device__ unsigned g_bsum[32];          // slice totals
__device__ unsigned g_boff[32];          // exclusive scan of slice totals
__device__ unsigned g_key[MAX_N];        // bucket | rank<<15
__device__ float4   g_xs[MAX_N];         // sorted (x,y,z, idx-as-bits)

struct Params { float resf[N_LEVELS]; };

// ------------------------------------------------------------------ morton
__device__ __forceinline__ unsigned expand_bits(unsigned v) {
    v = (v * 0x00010001u) & 0xFF0000FFu;
    v = (v * 0x00000101u) & 0x0F00F00Fu;
    v = (v * 0x00000011u) & 0xC30C30C3u;
    v = (v * 0x00000005u) & 0x49249249u;
    return v;
}

__device__ __forceinline__ unsigned bucket_of(float px, float py, float pz) {
    int cx = (int)(px * (float)SORT_RES);
    int cy = (int)(py * (float)SORT_RES);
    int cz = (int)(pz * (float)SORT_RES);
    cx = min(max(cx, 0), SORT_RES - 1);
    cy = min(max(cy, 0), SORT_RES - 1);
    cz = min(max(cz, 0), SORT_RES - 1);
    return expand_bits((unsigned)cx)
         | (expand_bits((unsigned)cy) << 1)
         | (expand_bits((unsigned)cz) << 2);
}

// ---------------------------------------------------------------- sorting
__global__ __launch_bounds__(TPB) void hist_kernel(const float* __restrict__ x, int N) {
    const int n0 = (blockIdx.x * TPB + threadIdx.x) * 4;
    if (n0 >= N) return;

    if (n0 + 3 < N) {
        // 4 points = 12 floats = 3 aligned float4 loads (48B*tid offset)
        const float4* xv = (const float4*)(x + n0 * 3);
        const float4 a = xv[0], b = xv[1], c = xv[2];
        const unsigned b0 = bucket_of(a.x, a.y, a.z);
        const unsigned b1 = bucket_of(a.w, b.x, b.y);
        const unsigned b2 = bucket_of(b.z, b.w, c.x);
        const unsigned b3 = bucket_of(c.y, c.z, c.w);
        const unsigned r0 = atomicAdd(&g_hist[b0], 1u);
        const unsigned r1 = atomicAdd(&g_hist[b1], 1u);
        const unsigned r2 = atomicAdd(&g_hist[b2], 1u);
        const unsigned r3 = atomicAdd(&g_hist[b3], 1u);
        *(uint4*)(g_key + n0) = make_uint4(b0 | (r0 << 15), b1 | (r1 << 15),
                                           b2 | (r2 << 15), b3 | (r3 << 15));
    } else {
        for (int n = n0; n < N; ++n) {
            const unsigned b = bucket_of(x[n * 3 + 0], x[n * 3 + 1], x[n * 3 + 2]);
            const unsigned r = atomicAdd(&g_hist[b], 1u);
            g_key[n] = b | (r << 15);
        }
    }
}

__global__ __launch_bounds__(1024) void scan_local_kernel() {   // grid = 32
    __shared__ unsigned sh[1024];
    const int t = threadIdx.x;
    const int i = blockIdx.x * 1024 + t;
    const unsigned v = g_hist[i];
    g_hist[i] = 0u;                     // restore zero-invariant
    sh[t] = v;
    __syncthreads();
    for (int d = 1; d < 1024; d <<= 1) {
        unsigned u = (t >= d) ? sh[t - d] : 0u;
        __syncthreads();
        sh[t] += u;
        __syncthreads();
    }
    g_base[i] = sh[t] - v;              // local exclusive
    if (t == 1023) g_bsum[blockIdx.x] = sh[t];
}

__global__ void scan_top_kernel() {     // 1 block, 32 threads
    const int t = threadIdx.x;
    const unsigned v = g_bsum[t];
    unsigned s = v;
    #pragma unroll
    for (int d = 1; d < 32; d <<= 1) {
        unsigned u = __shfl_up_sync(0xFFFFFFFFu, s, d);
        if (t >= d) s += u;
    }
    g_boff[t] = s - v;                  // exclusive
}

__global__ __launch_bounds__(TPB) void scatter_kernel(const float* __restrict__ x, int N) {
    const int n0 = (blockIdx.x * TPB + threadIdx.x) * 4;
    if (n0 >= N) return;

    if (n0 + 3 < N) {
        const uint4 k = *(const uint4*)(g_key + n0);
        const float4* xv = (const float4*)(x + n0 * 3);
        const float4 a = xv[0], b = xv[1], c = xv[2];

        const unsigned b0 = k.x & (N_BUCKETS - 1);
        const unsigned b1 = k.y & (N_BUCKETS - 1);
        const unsigned b2 = k.z & (N_BUCKETS - 1);
        const unsigned b3 = k.w & (N_BUCKETS - 1);

        const unsigned p0 = g_base[b0] + g_boff[b0 >> 10] + (k.x >> 15);
        const unsigned p1 = g_base[b1] + g_boff[b1 >> 10] + (k.y >> 15);
        const unsigned p2 = g_base[b2] + g_boff[b2 >> 10] + (k.z >> 15);
        const unsigned p3 = g_base[b3] + g_boff[b3 >> 10] + (k.w >> 15);

        g_xs[p0] = make_float4(a.x, a.y, a.z, __int_as_float(n0 + 0));
        g_xs[p1] = make_float4(a.w, b.x, b.y, __int_as_float(n0 + 1));
        g_xs[p2] = make_float4(b.z, b.w, c.x, __int_as_float(n0 + 2));
        g_xs[p3] = make_float4(c.y, c.z, c.w, __int_as_float(n0 + 3));
    } else {
        for (int n = n0; n < N; ++n) {
            const unsigned k = g_key[n];
            const unsigned bk = k & (N_BUCKETS - 1);
            const unsigned pos = g_base[bk] + g_boff[bk >> 10] + (k >> 15);
            g_xs[pos] = make_float4(x[n * 3 + 0], x[n * 3 + 1], x[n * 3 + 2],
                                    __int_as_float(n));
        }
    }
}

// ------------------------------------------------------------------- main
__global__ __launch_bounds__(TPB) void hashgrid_kernel(
    const float2* __restrict__ table,   // [T] float2
    float4* __restrict__ out,           // [N,8] float4 rows
    Params p, int N)
{
    __shared__ float4 s_row[TPB * ROW_PAD];   // 36 KB
    __shared__ int    s_n[TPB];

    const int tid  = threadIdx.x;
    const int lane = tid & 31;
    const int i = blockIdx.x * TPB + tid;
    const bool valid = (i < N);

    int n = -1;
    if (valid) {
        const float4 xi = g_xs[i];          // coalesced
        const float px = xi.x, py = xi.y, pz = xi.z;
        n = __float_as_int(xi.w);

        #pragma unroll
        for (int l = 0; l < N_LEVELS; l += 2) {
            float2 pr[2];
            #pragma unroll
            for (int s = 0; s < 2; ++s) {
                const float res = p.resf[l + s];
                const float sx = px * res;
                const float sy = py * res;
                const float sz = pz * res;

                const float fx = floorf(sx);
                const float fy = floorf(sy);
                const float fz = floorf(sz);

                const float dx = sx - fx;
                const float dy = sy - fy;
                const float dz = sz - fz;

                const unsigned x0u = (unsigned)(int)fx;
                const unsigned hy0 = (unsigned)(int)fy * P1;
                const unsigned hy1 = hy0 + P1;
                const unsigned hz0 = (unsigned)(int)fz * P2;
                const unsigned hz1 = hz0 + P2;

                const unsigned g00 = hy0 ^ hz0;
                const unsigned g10 = hy1 ^ hz0;
                const unsigned g01 = hy0 ^ hz1;
                const unsigned g11 = hy1 ^ hz1;

                const unsigned h000 = (x0u ^ g00) & T_MASK;
                const unsigned h010 = (x0u ^ g10) & T_MASK;
                const unsigned h001 = (x0u ^ g01) & T_MASK;
                const unsigned h011 = (x0u ^ g11) & T_MASK;

                const unsigned x1u  = x0u + 1u;
                const unsigned h100 = (x1u ^ g00) & T_MASK;
                const unsigned h110 = (x1u ^ g10) & T_MASK;
                const unsigned h101 = (x1u ^ g01) & T_MASK;
                const unsigned h111 = (x1u ^ g11) & T_MASK;

                const bool xeven = (x0u & 1u) == 0u;

                const float4 q00 = __ldg((const float4*)&table[h000 & ~1u]);
                const float4 q10 = __ldg((const float4*)&table[h010 & ~1u]);
                const float4 q01 = __ldg((const float4*)&table[h001 & ~1u]);
                const float4 q11 = __ldg((const float4*)&table[h011 & ~1u]);

                float2 e00, e10, e01, e11;
                if (!xeven) {
                    e00 = __ldg(&table[h100]);
                    e10 = __ldg(&table[h110]);
                    e01 = __ldg(&table[h101]);
                    e11 = __ldg(&table[h111]);
                }

                const float2 q00lo = make_float2(q00.x, q00.y), q00hi = make_float2(q00.z, q00.w);
                const float2 q10lo = make_float2(q10.x, q10.y), q10hi = make_float2(q10.z, q10.w);
                const float2 q01lo = make_float2(q01.x, q01.y), q01hi = make_float2(q01.z, q01.w);
                const float2 q11lo = make_float2(q11.x, q11.y), q11hi = make_float2(q11.z, q11.w);

                const bool p00 = (h000 & 1u), p10 = (h010 & 1u),
                           p01 = (h001 & 1u), p11 = (h011 & 1u);

                const float2 v000 = p00 ? q00hi : q00lo;
                const float2 v010 = p10 ? q10hi : q10lo;
                const float2 v001 = p01 ? q01hi : q01lo;
                const float2 v011 = p11 ? q11hi : q11lo;

                const float2 v100 = xeven ? (p00 ? q00lo : q00hi) : e00;
                const float2 v110 = xeven ? (p10 ? q10lo : q10hi) : e10;
                const float2 v101 = xeven ? (p01 ? q01lo : q01hi) : e01;
                const float2 v111 = xeven ? (p11 ? q11lo : q11hi) : e11;

                const float wx0 = 1.0f - dx, wx1 = dx;
                const float wy0 = 1.0f - dy, wy1 = dy;
                const float wz0 = 1.0f - dz, wz1 = dz;

                float a00x = v000.x * wx0 + v100.x * wx1;
                float a00y = v000.y * wx0 + v100.y * wx1;
                float a10x = v010.x * wx0 + v110.x * wx1;
                float a10y = v010.y * wx0 + v110.y * wx1;
                float a01x = v001.x * wx0 + v101.x * wx1;
                float a01y = v001.y * wx0 + v101.y * wx1;
                float a11x = v011.x * wx0 + v111.x * wx1;
                float a11y = v011.y * wx0 + v111.y * wx1;

                float b0x = a00x * wy0 + a10x * wy1;
                float b0y = a00y * wy0 + a10y * wy1;
                float b1x = a01x * wy0 + a11x * wy1;
                float b1y = a01y * wy0 + a11y * wy1;

                pr[s].x = b0x * wz0 + b1x * wz1;
                pr[s].y = b0y * wz0 + b1y * wz1;
            }
            s_row[tid * ROW_PAD + (l >> 1)] =
                make_float4(pr[0].x, pr[0].y, pr[1].x, pr[1].y);
        }
    }
    s_n[tid] = n;
    __syncwarp();

    // Warp transpose store: 4 groups of 8 lanes each write one full 128B
    // output row contiguously -> 4 wavefronts per STG.128.
    const int wbase = tid & ~31;
    const int chunk = lane & 7;
    #pragma unroll
    for (int iter = 0; iter < 8; ++iter) {
        const int row = wbase + iter * 4 + (lane >> 3);
        const int nn = s_n[row];
        if (nn >= 0) {
            __stcs(&out[(size_t)nn * 8 + chunk], s_row[row * ROW_PAD + chunk]);
        }
    }
}

// ----------------------------------------------------------------- launch
extern "C" void kernel_launch(void* const* d_in, const int* in_sizes, int n_in,
                              void* d_out, int out_size)
{
    const float*  x     = (const float*)d_in[0];
    const float2* table = (const float2*)d_in[1];
    float4*       out   = (float4*)d_out;

    const int N = in_sizes[0] / 3;

    Params p;
    {
        const double growth = exp((log(128.0) - log(16.0)) / (double)(N_LEVELS - 1));
        for (int l = 0; l < N_LEVELS; ++l)
            p.resf[l] = (float)floor(16.0 * pow(growth, (double)l));
    }

    const int pb4 = ((N + 3) / 4 + TPB - 1) / TPB;   // 4 points per thread
    const int pb  = (N + TPB - 1) / TPB;

    hist_kernel<<<pb4, TPB>>>(x, N);
    scan_local_kernel<<<32, 1024>>>();
    scan_top_kernel<<<1, 32>>>();
    scatter_kernel<<<pb4, TPB>>>(x, N);
    hashgrid_kernel<<<pb, TPB>>>(table, out, p, N);
}